// round 12
// baseline (speedup 1.0000x reference)
#include <cuda_runtime.h>
#include <cuda_fp16.h>
#include <cstdint>

#define DEV_INLINE __device__ __forceinline__

// Problem shape (fixed)
static constexpr int Bb = 256, Tt = 256, Ii = 2048, Hh = 128;
static constexpr int Mtot = Bb * Tt;      // 65536 rows of xp
static constexpr int TCH  = 128;          // timesteps per pipeline chunk (2 chunks)
static constexpr int MT   = 128;          // M rows per CTA (one batch row's chunk)
static constexpr int NT   = 128;          // N (= full H)
static constexpr int KT   = 32;           // K floats per tile
static constexpr int NKT  = Ii / KT;      // 64 K tiles
// fp16 smem tiles: 64 bytes per row (32 fp16)
static constexpr int A_BYTES = MT * 64;           // 8 KB
static constexpr int B_BYTES = NT * 64;           // 8 KB
static constexpr int STAGE_BYTES = A_BYTES + B_BYTES;   // 16 KB
static constexpr int STAGES = 4;
// Request 120KB: only 65KB used; padding forces 1 gemm CTA/SM so an rnn CTA
// (27.6k regs) can co-reside in the remaining register file.
static constexpr int SMEM_ALLOC = 120 * 1024;

// Scratch: xp[m][h] (32 MB); h carry between rnn chunks
__device__ float g_xp[(size_t)Mtot * Hh];
__device__ float g_h[(size_t)Bb * Hh];

// ---------------- helpers ----------------
DEV_INLINE uint32_t smem_u32(const void* p) {
    uint32_t a;
    asm("{ .reg .u64 t; cvta.to.shared.u64 t, %1; cvt.u32.u64 %0, t; }" : "=r"(a) : "l"(p));
    return a;
}
DEV_INLINE void ldsm_x4(uint32_t& r0, uint32_t& r1, uint32_t& r2, uint32_t& r3, uint32_t a) {
    asm volatile("ldmatrix.sync.aligned.m8n8.x4.shared.b16 {%0,%1,%2,%3}, [%4];"
                 : "=r"(r0), "=r"(r1), "=r"(r2), "=r"(r3) : "r"(a));
}
DEV_INLINE void ldsm_x2(uint32_t& r0, uint32_t& r1, uint32_t a) {
    asm volatile("ldmatrix.sync.aligned.m8n8.x2.shared.b16 {%0,%1}, [%2];"
                 : "=r"(r0), "=r"(r1) : "r"(a));
}
DEV_INLINE void mma_f16(float* c, uint32_t a0, uint32_t a1, uint32_t a2, uint32_t a3,
                        uint32_t b0, uint32_t b1) {
    asm volatile("mma.sync.aligned.m16n8k16.row.col.f32.f16.f16.f32 "
                 "{%0,%1,%2,%3}, {%4,%5,%6,%7}, {%8,%9}, {%0,%1,%2,%3};"
                 : "+f"(c[0]), "+f"(c[1]), "+f"(c[2]), "+f"(c[3])
                 : "r"(a0), "r"(a1), "r"(a2), "r"(a3), "r"(b0), "r"(b1));
}
DEV_INLINE uint32_t f2h2(float a, float b) {
    __half2 h = __floats2half2_rn(a, b);
    return *reinterpret_cast<uint32_t*>(&h);
}
DEV_INLINE void sts128(uint32_t addr, uint32_t r0, uint32_t r1, uint32_t r2, uint32_t r3) {
    asm volatile("st.shared.v4.b32 [%0], {%1,%2,%3,%4};"
                 :: "r"(addr), "r"(r0), "r"(r1), "r"(r2), "r"(r3));
}
// Blackwell packed fp32x2 math (PTX ISA 8.6, sm_100+)
DEV_INLINE uint64_t fma2(uint64_t a, uint64_t b, uint64_t c) {
    uint64_t d;
    asm("fma.rn.f32x2 %0, %1, %2, %3;" : "=l"(d) : "l"(a), "l"(b), "l"(c));
    return d;
}
DEV_INLINE uint64_t add2(uint64_t a, uint64_t b) {
    uint64_t d;
    asm("add.rn.f32x2 %0, %1, %2;" : "=l"(d) : "l"(a), "l"(b));
    return d;
}
DEV_INLINE float lo32(uint64_t v) { return __uint_as_float((uint32_t)v); }
DEV_INLINE float hi32(uint64_t v) { return __uint_as_float((uint32_t)(v >> 32)); }

// ---------------- Kernel A: xp chunk GEMM, fp16 m16n8k16 ----------------
// CTA = batch row blockIdx.x, timesteps [tb, tb+128): 128x128 tile, K=2048.
// 256 threads, 8 warps (2M x 4N), warp tile 64x32 -> acc only 64 regs/thread.
// __launch_bounds__(256,2) caps regs at 128 so one rnn CTA co-resides per SM.
__global__ void __launch_bounds__(256, 2) xp_gemm(
    const float* __restrict__ x, const float* __restrict__ Wih,
    const float* __restrict__ bih, const float* __restrict__ bhh, int tb)
{
    extern __shared__ char dsm[];
    __shared__ float s_bias[NT];

    const int tid = threadIdx.x;
    const int wid = tid >> 5, lane = tid & 31;
    const int warp_m = wid >> 2, warp_n = wid & 3;        // 2 x 4
    const int g = lane >> 2, tig = lane & 3;
    const uint32_t base = (smem_u32(dsm) + 1023u) & ~1023u;
    const size_t m_base = (size_t)blockIdx.x * Tt + tb;   // 128 consecutive m-rows

    if (tid < NT) s_bias[tid] = bih[tid] + bhh[tid];

    // granule mapping: 256 thr cover 128 rows x 4 chunks in 2 iterations
    const int gr = tid >> 2, gc = tid & 3;   // gr in [0,64), rows gr + i*64

    float4 la[2][2], lb[2][2];      // reg staging (raw fp32, converted at STS)

    auto ldg_stage = [&](int kc) {
        #pragma unroll
        for (int i = 0; i < 2; i++) {
            const float* pA = x + (m_base + gr + i * 64) * Ii + kc * KT + gc * 8;
            la[i][0] = *reinterpret_cast<const float4*>(pA);
            la[i][1] = *reinterpret_cast<const float4*>(pA + 4);
        }
        #pragma unroll
        for (int i = 0; i < 2; i++) {
            const float* pB = Wih + (size_t)(gr + i * 64) * Ii + kc * KT + gc * 8;
            lb[i][0] = *reinterpret_cast<const float4*>(pB);
            lb[i][1] = *reinterpret_cast<const float4*>(pB + 4);
        }
    };
    auto sts_stage = [&](int s) {
        const uint32_t sA = base + s * STAGE_BYTES;
        const uint32_t sB = sA + A_BYTES;
        #pragma unroll
        for (int i = 0; i < 2; i++) {
            int row = gr + i * 64;
            uint32_t off = row * 64 + ((gc ^ ((row >> 1) & 3)) << 4);
            sts128(sA + off, f2h2(la[i][0].x, la[i][0].y), f2h2(la[i][0].z, la[i][0].w),
                             f2h2(la[i][1].x, la[i][1].y), f2h2(la[i][1].z, la[i][1].w));
        }
        #pragma unroll
        for (int i = 0; i < 2; i++) {
            int row = gr + i * 64;
            uint32_t off = row * 64 + ((gc ^ ((row >> 1) & 3)) << 4);
            sts128(sB + off, f2h2(lb[i][0].x, lb[i][0].y), f2h2(lb[i][0].z, lb[i][0].w),
                             f2h2(lb[i][1].x, lb[i][1].y), f2h2(lb[i][1].z, lb[i][1].w));
        }
    };

    // ldmatrix per-lane address components (r5-proven mapping, new extents)
    const int am = lane >> 3, aj = lane & 7;
    const int a_row  = warp_m * 64 + (am & 1) * 8 + aj;       // + ma*16
    const int a_csel = am >> 1;
    const int bm = (lane & 15) >> 3, bj = lane & 7;
    const int b_row  = warp_n * 32 + bj;                      // + na*8
    uint32_t aswz[2], bswz[2];
    #pragma unroll
    for (int s2 = 0; s2 < 2; s2++) {
        aswz[s2] = (uint32_t)(((s2 * 2 + a_csel) ^ ((a_row >> 1) & 3)) << 4);
        bswz[s2] = (uint32_t)(((s2 * 2 + bm)     ^ ((b_row >> 1) & 3)) << 4);
    }

    float acc[4][4][4];
    #pragma unroll
    for (int ma = 0; ma < 4; ma++)
        #pragma unroll
        for (int na = 0; na < 4; na++)
            #pragma unroll
            for (int q = 0; q < 4; q++) acc[ma][na][q] = 0.0f;

    // prologue: stages 0,1 in smem; regs hold stage 2
    ldg_stage(0); sts_stage(0);
    ldg_stage(1); sts_stage(1);
    ldg_stage(2);

    for (int kc = 0; kc < NKT; kc++) {
        if (kc + 2 < NKT) sts_stage((kc + 2) & 3);   // regs (loaded last iter) -> smem
        if (kc + 3 < NKT) ldg_stage(kc + 3);          // refill regs
        __syncthreads();   // single barrier per iter (ring-distance proof, r5 notes)

        const uint32_t sA = base + (kc & 3) * STAGE_BYTES;
        const uint32_t sB = sA + A_BYTES;
        const uint32_t aA = sA + a_row * 64;
        const uint32_t aB = sB + b_row * 64;

        #pragma unroll
        for (int st = 0; st < 2; st++) {              // two k16 steps per tile
            uint32_t a[4][4], b[4][2];
            #pragma unroll
            for (int ma = 0; ma < 4; ma++)
                ldsm_x4(a[ma][0], a[ma][1], a[ma][2], a[ma][3], aA + ma * 1024 + aswz[st]);
            #pragma unroll
            for (int na = 0; na < 4; na++)
                ldsm_x2(b[na][0], b[na][1], aB + na * 512 + bswz[st]);
            #pragma unroll
            for (int ma = 0; ma < 4; ma++)
                #pragma unroll
                for (int na = 0; na < 4; na++)
                    mma_f16(acc[ma][na], a[ma][0], a[ma][1], a[ma][2], a[ma][3],
                            b[na][0], b[na][1]);
        }
    }

    // epilogue: + bias -> g_xp (float2 stores, C-fragment layout)
    const int n0 = warp_n * 32 + tig * 2;
    float2 biasv[4];
    #pragma unroll
    for (int na = 0; na < 4; na++) {
        biasv[na].x = s_bias[n0 + na * 8];
        biasv[na].y = s_bias[n0 + na * 8 + 1];
    }
    const int r0 = warp_m * 64 + g;
    #pragma unroll
    for (int ma = 0; ma < 4; ma++) {
        float* p0 = g_xp + (m_base + r0 + ma * 16) * Hh;
        float* p1 = p0 + (size_t)8 * Hh;
        #pragma unroll
        for (int na = 0; na < 4; na++) {
            int col = n0 + na * 8;
            float2 v0 = make_float2(acc[ma][na][0] + biasv[na].x, acc[ma][na][1] + biasv[na].y);
            float2 v1 = make_float2(acc[ma][na][2] + biasv[na].x, acc[ma][na][3] + biasv[na].y);
            *reinterpret_cast<float2*>(p0 + col) = v0;
            *reinterpret_cast<float2*>(p1 + col) = v1;
        }
    }
}

// ---------------- Kernel B: 128-step tanh-RNN chunk (+ optional final FC) ----------------
// r5-proven internals; h carried across chunks via g_h.
__global__ void __launch_bounds__(128, 2) rnn_tail(
    const float* __restrict__ Whh, const float* __restrict__ Wfc,
    const float* __restrict__ bfc, float* __restrict__ out,
    int tb, int init_h, int do_fc)
{
    __shared__ __align__(16) float hbuf[2][128];
    __shared__ float red[4];
    const int j = threadIdx.x;
    const int b = blockIdx.x;

    uint64_t w64[64];                       // Whh row j as 64 packed fp32 pairs
    #pragma unroll
    for (int i = 0; i < 32; i++) {
        ulonglong2 v = *reinterpret_cast<const ulonglong2*>(Whh + (size_t)j * Hh + i * 4);
        w64[2 * i]     = v.x;
        w64[2 * i + 1] = v.y;
    }
    const float wfc = Wfc[j];
    hbuf[0][j] = init_h ? 0.0f : g_h[(size_t)b * Hh + j];
    __syncthreads();

    const float* xrow = g_xp + ((size_t)b * Tt + tb) * Hh + j;
    float xv = xrow[0];
    float x1 = xrow[Hh];

    for (int t = 0; t < TCH; t++) {
        float x2 = (t + 2 < TCH) ? xrow[(size_t)(t + 2) * Hh] : 0.0f;  // dist-2, chunk-clamped
        const uint64_t* hb = reinterpret_cast<const uint64_t*>(hbuf[t & 1]);
        uint64_t c0 = (uint64_t)__float_as_uint(xv);    // lo = xv, hi = 0
        uint64_t c1 = 0, c2 = 0, c3 = 0;
        #pragma unroll
        for (int k = 0; k < 16; k++) {
            ulonglong2 p0 = *reinterpret_cast<const ulonglong2*>(hb + 4 * k);
            ulonglong2 p1 = *reinterpret_cast<const ulonglong2*>(hb + 4 * k + 2);
            c0 = fma2(p0.x, w64[4 * k + 0], c0);
            c1 = fma2(p0.y, w64[4 * k + 1], c1);
            c2 = fma2(p1.x, w64[4 * k + 2], c2);
            c3 = fma2(p1.y, w64[4 * k + 3], c3);
        }
        uint64_t s = add2(add2(c0, c1), add2(c2, c3));
        float a = lo32(s) + hi32(s);
        float u  = __expf(2.0f * a);
        float hn = 1.0f - __fdividef(2.0f, u + 1.0f);
        hbuf[(t + 1) & 1][j] = hn;
        xv = x1; x1 = x2;
        __syncthreads();
    }

    // TCH even -> final h of this chunk is in hbuf[0]
    if (do_fc) {
        float v = wfc * hbuf[0][j];
        #pragma unroll
        for (int o = 16; o > 0; o >>= 1) v += __shfl_down_sync(0xFFFFFFFFu, v, o);
        if ((j & 31) == 0) red[j >> 5] = v;
        __syncthreads();
        if (j == 0) out[b] = red[0] + red[1] + red[2] + red[3] + bfc[0];
    } else {
        g_h[(size_t)b * Hh + j] = hbuf[0][j];
    }
}

// ---------------- launch: 2-chunk software pipeline via in-capture stream fork ----------------
extern "C" void kernel_launch(void* const* d_in, const int* in_sizes, int n_in,
                              void* d_out, int out_size)
{
    const float* x   = (const float*)d_in[0];
    const float* Wih = (const float*)d_in[1];
    const float* Whh = (const float*)d_in[2];
    const float* bih = (const float*)d_in[3];
    const float* bhh = (const float*)d_in[4];
    const float* Wfc = (const float*)d_in[5];
    const float* bfc = (const float*)d_in[6];
    float* out = (float*)d_out;

    cudaFuncSetAttribute(xp_gemm, cudaFuncAttributeMaxDynamicSharedMemorySize, SMEM_ALLOC);

    cudaStream_t s1;
    cudaEvent_t e0, e1, fin;
    cudaStreamCreateWithFlags(&s1, cudaStreamNonBlocking);
    cudaEventCreateWithFlags(&e0, cudaEventDisableTiming);
    cudaEventCreateWithFlags(&e1, cudaEventDisableTiming);
    cudaEventCreateWithFlags(&fin, cudaEventDisableTiming);

    // chunk 0 GEMM on the origin stream, then chunk 1 GEMM
    xp_gemm<<<Bb, 256, SMEM_ALLOC>>>(x, Wih, bih, bhh, 0);
    cudaEventRecord(e0, 0);
    xp_gemm<<<Bb, 256, SMEM_ALLOC>>>(x, Wih, bih, bhh, TCH);
    cudaEventRecord(e1, 0);

    // rnn chunks on the forked stream: r0 co-resides with g1 (reg budget engineered)
    cudaStreamWaitEvent(s1, e0, 0);
    rnn_tail<<<Bb, 128, 0, s1>>>(Whh, Wfc, bfc, out, 0,   1, 0);
    cudaStreamWaitEvent(s1, e1, 0);
    rnn_tail<<<Bb, 128, 0, s1>>>(Whh, Wfc, bfc, out, TCH, 0, 1);

    // rejoin the origin stream before capture ends
    cudaEventRecord(fin, s1);
    cudaStreamWaitEvent(0, fin, 0);
}

// round 13
// speedup vs baseline: 1.2962x; 1.2962x over previous
#include <cuda_runtime.h>
#include <cuda_fp16.h>
#include <cstdint>

#define DEV_INLINE __device__ __forceinline__

// Problem shape (fixed)
static constexpr int Bb = 256, Tt = 256, Ii = 2048, Hh = 128;
static constexpr int Mtot = Bb * Tt;      // 65536 rows of xp
static constexpr int TCH  = 128;          // timesteps per chunk (2 chunks)
static constexpr int MT   = 128;          // M rows per gemm CTA
static constexpr int NT   = 128;          // N (= full H)
static constexpr int KT   = 32;           // K floats per tile
static constexpr int NKT  = Ii / KT;      // 64 K tiles
static constexpr int A_BYTES = MT * 64;           // 8 KB
static constexpr int B_BYTES = NT * 64;           // 8 KB
static constexpr int STAGE_BYTES = A_BYTES + B_BYTES;   // 16 KB
static constexpr int STAGES = 4;
static constexpr int SMEM_TOTAL = STAGES * STAGE_BYTES + 1024;   // 65.5 KB

// Scratch + handshake state
__device__ float g_xp[(size_t)Mtot * Hh];
__device__ float g_h[(size_t)Bb * Hh];
__device__ volatile int g_fc0[Bb];   // gemm chunk0 done per b
__device__ volatile int g_fc1[Bb];   // gemm chunk1 done per b
__device__ volatile int g_fh[Bb];    // rnn chunk0 done per b

// ---------------- helpers ----------------
DEV_INLINE uint32_t smem_u32(const void* p) {
    uint32_t a;
    asm("{ .reg .u64 t; cvta.to.shared.u64 t, %1; cvt.u32.u64 %0, t; }" : "=r"(a) : "l"(p));
    return a;
}
DEV_INLINE void ldsm_x4(uint32_t& r0, uint32_t& r1, uint32_t& r2, uint32_t& r3, uint32_t a) {
    asm volatile("ldmatrix.sync.aligned.m8n8.x4.shared.b16 {%0,%1,%2,%3}, [%4];"
                 : "=r"(r0), "=r"(r1), "=r"(r2), "=r"(r3) : "r"(a));
}
DEV_INLINE void ldsm_x2(uint32_t& r0, uint32_t& r1, uint32_t a) {
    asm volatile("ldmatrix.sync.aligned.m8n8.x2.shared.b16 {%0,%1}, [%2];"
                 : "=r"(r0), "=r"(r1) : "r"(a));
}
DEV_INLINE void mma_f16(float* c, uint32_t a0, uint32_t a1, uint32_t a2, uint32_t a3,
                        uint32_t b0, uint32_t b1) {
    asm volatile("mma.sync.aligned.m16n8k16.row.col.f32.f16.f16.f32 "
                 "{%0,%1,%2,%3}, {%4,%5,%6,%7}, {%8,%9}, {%0,%1,%2,%3};"
                 : "+f"(c[0]), "+f"(c[1]), "+f"(c[2]), "+f"(c[3])
                 : "r"(a0), "r"(a1), "r"(a2), "r"(a3), "r"(b0), "r"(b1));
}
DEV_INLINE uint32_t f2h2(float a, float b) {
    __half2 h = __floats2half2_rn(a, b);
    return *reinterpret_cast<uint32_t*>(&h);
}
DEV_INLINE void sts128(uint32_t addr, uint32_t r0, uint32_t r1, uint32_t r2, uint32_t r3) {
    asm volatile("st.shared.v4.b32 [%0], {%1,%2,%3,%4};"
                 :: "r"(addr), "r"(r0), "r"(r1), "r"(r2), "r"(r3));
}
DEV_INLINE uint64_t fma2(uint64_t a, uint64_t b, uint64_t c) {
    uint64_t d;
    asm("fma.rn.f32x2 %0, %1, %2, %3;" : "=l"(d) : "l"(a), "l"(b), "l"(c));
    return d;
}
DEV_INLINE uint64_t add2(uint64_t a, uint64_t b) {
    uint64_t d;
    asm("add.rn.f32x2 %0, %1, %2;" : "=l"(d) : "l"(a), "l"(b));
    return d;
}
DEV_INLINE float lo32(uint64_t v) { return __uint_as_float((uint32_t)v); }
DEV_INLINE float hi32(uint64_t v) { return __uint_as_float((uint32_t)(v >> 32)); }
DEV_INLINE void spin_until(volatile int* f) {
    while (*f == 0) __nanosleep(64);
}

// ---------------- gemm role (r11's proven 128-thread body) ----------------
__device__ void gemm_role(char* dsm,
    const float* __restrict__ x, const float* __restrict__ Wih,
    const float* __restrict__ bih, const float* __restrict__ bhh, int tb, int b)
{
    __shared__ float s_bias[NT];

    const int tid = threadIdx.x;
    const int wid = tid >> 5, lane = tid & 31;
    const int warp_m = wid >> 1, warp_n = wid & 1;        // 2 x 2
    const int g = lane >> 2, tig = lane & 3;
    const uint32_t base = (smem_u32(dsm) + 1023u) & ~1023u;
    const size_t m_base = (size_t)b * Tt + tb;            // 128 consecutive m-rows

    s_bias[tid] = bih[tid] + bhh[tid];

    const int gr = tid >> 2, gc = tid & 3;

    float4 la[4][2], lb[4][2];      // reg staging (raw fp32, converted at STS)

    auto ldg_stage = [&](int kc) {
        const float* pA = x + (m_base + gr) * Ii + kc * KT + gc * 8;
        #pragma unroll
        for (int i = 0; i < 4; i++) {
            la[i][0] = *reinterpret_cast<const float4*>(pA + (size_t)i * 32 * Ii);
            la[i][1] = *reinterpret_cast<const float4*>(pA + (size_t)i * 32 * Ii + 4);
        }
        const float* pB = Wih + (size_t)gr * Ii + kc * KT + gc * 8;
        #pragma unroll
        for (int i = 0; i < 4; i++) {
            lb[i][0] = *reinterpret_cast<const float4*>(pB + (size_t)i * 32 * Ii);
            lb[i][1] = *reinterpret_cast<const float4*>(pB + (size_t)i * 32 * Ii + 4);
        }
    };
    auto sts_stage = [&](int s) {
        const uint32_t sA = base + s * STAGE_BYTES;
        const uint32_t sB = sA + A_BYTES;
        #pragma unroll
        for (int i = 0; i < 4; i++) {
            int row = gr + i * 32;
            uint32_t off = row * 64 + ((gc ^ ((row >> 1) & 3)) << 4);
            sts128(sA + off, f2h2(la[i][0].x, la[i][0].y), f2h2(la[i][0].z, la[i][0].w),
                             f2h2(la[i][1].x, la[i][1].y), f2h2(la[i][1].z, la[i][1].w));
        }
        #pragma unroll
        for (int i = 0; i < 4; i++) {
            int row = gr + i * 32;
            uint32_t off = row * 64 + ((gc ^ ((row >> 1) & 3)) << 4);
            sts128(sB + off, f2h2(lb[i][0].x, lb[i][0].y), f2h2(lb[i][0].z, lb[i][0].w),
                             f2h2(lb[i][1].x, lb[i][1].y), f2h2(lb[i][1].z, lb[i][1].w));
        }
    };

    const int am = lane >> 3, aj = lane & 7;
    const int a_row  = warp_m * 64 + (am & 1) * 8 + aj;       // + ma*16
    const int a_csel = am >> 1;
    const int bm = (lane & 15) >> 3, bj = lane & 7;
    const int b_row  = warp_n * 64 + bj;                      // + na*8
    uint32_t aswz[2], bswz[2];
    #pragma unroll
    for (int s2 = 0; s2 < 2; s2++) {
        aswz[s2] = (uint32_t)(((s2 * 2 + a_csel) ^ ((a_row >> 1) & 3)) << 4);
        bswz[s2] = (uint32_t)(((s2 * 2 + bm)     ^ ((b_row >> 1) & 3)) << 4);
    }

    float acc[4][8][4];
    #pragma unroll
    for (int ma = 0; ma < 4; ma++)
        #pragma unroll
        for (int na = 0; na < 8; na++)
            #pragma unroll
            for (int q = 0; q < 4; q++) acc[ma][na][q] = 0.0f;

    ldg_stage(0); sts_stage(0);
    ldg_stage(1); sts_stage(1);
    ldg_stage(2);

    for (int kc = 0; kc < NKT; kc++) {
        if (kc + 2 < NKT) sts_stage((kc + 2) & 3);
        if (kc + 3 < NKT) ldg_stage(kc + 3);
        __syncthreads();

        const uint32_t sA = base + (kc & 3) * STAGE_BYTES;
        const uint32_t sB = sA + A_BYTES;
        const uint32_t aA = sA + a_row * 64;
        const uint32_t aB = sB + b_row * 64;

        #pragma unroll
        for (int st = 0; st < 2; st++) {
            uint32_t a[4][4], bfr[8][2];
            #pragma unroll
            for (int ma = 0; ma < 4; ma++)
                ldsm_x4(a[ma][0], a[ma][1], a[ma][2], a[ma][3], aA + ma * 1024 + aswz[st]);
            #pragma unroll
            for (int na = 0; na < 8; na++)
                ldsm_x2(bfr[na][0], bfr[na][1], aB + na * 512 + bswz[st]);
            #pragma unroll
            for (int ma = 0; ma < 4; ma++)
                #pragma unroll
                for (int na = 0; na < 8; na++)
                    mma_f16(acc[ma][na], a[ma][0], a[ma][1], a[ma][2], a[ma][3],
                            bfr[na][0], bfr[na][1]);
        }
    }

    const int n0 = warp_n * 64 + tig * 2;
    float2 biasv[8];
    #pragma unroll
    for (int na = 0; na < 8; na++) {
        biasv[na].x = s_bias[n0 + na * 8];
        biasv[na].y = s_bias[n0 + na * 8 + 1];
    }
    const int r0 = warp_m * 64 + g;
    #pragma unroll
    for (int ma = 0; ma < 4; ma++) {
        float* p0 = g_xp + (m_base + r0 + ma * 16) * Hh;
        float* p1 = p0 + (size_t)8 * Hh;
        #pragma unroll
        for (int na = 0; na < 8; na++) {
            int col = n0 + na * 8;
            float2 v0 = make_float2(acc[ma][na][0] + biasv[na].x, acc[ma][na][1] + biasv[na].y);
            float2 v1 = make_float2(acc[ma][na][2] + biasv[na].x, acc[ma][na][3] + biasv[na].y);
            *reinterpret_cast<float2*>(p0 + col) = v0;
            *reinterpret_cast<float2*>(p1 + col) = v1;
        }
    }

    // publish: all stores done -> release flag
    __syncthreads();
    __threadfence();
    if (tid == 0) {
        if (tb == 0) g_fc0[b] = 1; else g_fc1[b] = 1;
    }
}

// ---------------- rnn role: 128 steps (r5-proven internals) ----------------
__device__ void rnn_role(
    const float* __restrict__ Whh, const float* __restrict__ Wfc,
    const float* __restrict__ bfc, float* __restrict__ out, int b, int chunk)
{
    __shared__ __align__(16) float hbuf[2][128];
    __shared__ float red[4];
    const int j = threadIdx.x;
    const int tb = chunk * TCH;

    uint64_t w64[64];                       // Whh row j as 64 packed fp32 pairs
    #pragma unroll
    for (int i = 0; i < 32; i++) {
        ulonglong2 v = *reinterpret_cast<const ulonglong2*>(Whh + (size_t)j * Hh + i * 4);
        w64[2 * i]     = v.x;
        w64[2 * i + 1] = v.y;
    }
    const float wfc = Wfc[j];

    // acquire producers
    if (j == 0) {
        if (chunk == 0) { spin_until(&g_fc0[b]); }
        else            { spin_until(&g_fc1[b]); spin_until(&g_fh[b]); }
        __threadfence();
    }
    __syncthreads();

    hbuf[0][j] = (chunk == 0) ? 0.0f : g_h[(size_t)b * Hh + j];
    __syncthreads();

    const float* xrow = g_xp + ((size_t)b * Tt + tb) * Hh + j;
    float xv = xrow[0];
    float x1 = xrow[Hh];

    for (int t = 0; t < TCH; t++) {
        float x2 = (t + 2 < TCH) ? xrow[(size_t)(t + 2) * Hh] : 0.0f;  // dist-2, chunk-clamped
        const uint64_t* hb = reinterpret_cast<const uint64_t*>(hbuf[t & 1]);
        uint64_t c0 = (uint64_t)__float_as_uint(xv);
        uint64_t c1 = 0, c2 = 0, c3 = 0;
        #pragma unroll
        for (int k = 0; k < 16; k++) {
            ulonglong2 p0 = *reinterpret_cast<const ulonglong2*>(hb + 4 * k);
            ulonglong2 p1 = *reinterpret_cast<const ulonglong2*>(hb + 4 * k + 2);
            c0 = fma2(p0.x, w64[4 * k + 0], c0);
            c1 = fma2(p0.y, w64[4 * k + 1], c1);
            c2 = fma2(p1.x, w64[4 * k + 2], c2);
            c3 = fma2(p1.y, w64[4 * k + 3], c3);
        }
        uint64_t s = add2(add2(c0, c1), add2(c2, c3));
        float a = lo32(s) + hi32(s);
        float u  = __expf(2.0f * a);
        float hn = 1.0f - __fdividef(2.0f, u + 1.0f);
        hbuf[(t + 1) & 1][j] = hn;
        xv = x1; x1 = x2;
        __syncthreads();
    }

    // TCH even -> final h of this chunk is in hbuf[0]
    if (chunk == 0) {
        g_h[(size_t)b * Hh + j] = hbuf[0][j];
        __threadfence();
        __syncthreads();
        if (j == 0) g_fh[b] = 1;
    } else {
        float v = wfc * hbuf[0][j];
        #pragma unroll
        for (int o = 16; o > 0; o >>= 1) v += __shfl_down_sync(0xFFFFFFFFu, v, o);
        if ((j & 31) == 0) red[j >> 5] = v;
        __syncthreads();
        if (j == 0) out[b] = red[0] + red[1] + red[2] + red[3] + bfc[0];
    }
}

// ---------------- fused kernel: roles by blockIdx ----------------
// bids [0,256):      gemm c0, b = bid
// bids [256,768):    k = bid-256; even k -> gemm c1 b=k/2; odd k -> rnn c0 b=k/2
// bids [768,1024):   rnn c1, b = bid-768
__global__ void __launch_bounds__(128, 2) fused(
    const float* __restrict__ x, const float* __restrict__ Wih,
    const float* __restrict__ Whh,
    const float* __restrict__ bih, const float* __restrict__ bhh,
    const float* __restrict__ Wfc, const float* __restrict__ bfc,
    float* __restrict__ out)
{
    extern __shared__ char dsm[];
    const int bid = blockIdx.x;
    if (bid < Bb) {
        gemm_role(dsm, x, Wih, bih, bhh, 0, bid);
    } else if (bid < 3 * Bb) {
        const int k = bid - Bb;
        const int b = k >> 1;
        if ((k & 1) == 0) gemm_role(dsm, x, Wih, bih, bhh, TCH, b);
        else              rnn_role(Whh, Wfc, bfc, out, b, 0);
    } else {
        rnn_role(Whh, Wfc, bfc, out, bid - 3 * Bb, 1);
    }
}

__global__ void flag_init() {
    const int i = blockIdx.x * blockDim.x + threadIdx.x;
    if (i < Bb) { g_fc0[i] = 0; g_fc1[i] = 0; g_fh[i] = 0; }
}

// ---------------- launch ----------------
extern "C" void kernel_launch(void* const* d_in, const int* in_sizes, int n_in,
                              void* d_out, int out_size)
{
    const float* x   = (const float*)d_in[0];
    const float* Wih = (const float*)d_in[1];
    const float* Whh = (const float*)d_in[2];
    const float* bih = (const float*)d_in[3];
    const float* bhh = (const float*)d_in[4];
    const float* Wfc = (const float*)d_in[5];
    const float* bfc = (const float*)d_in[6];
    float* out = (float*)d_out;

    cudaFuncSetAttribute(fused, cudaFuncAttributeMaxDynamicSharedMemorySize, SMEM_TOTAL);

    flag_init<<<2, 128>>>();
    fused<<<4 * Bb, 128, SMEM_TOTAL>>>(x, Wih, Whh, bih, bhh, Wfc, bfc, out);
}